// round 7
// baseline (speedup 1.0000x reference)
#include <cuda_runtime.h>
#include <cuda_fp16.h>
#include <math.h>

#define NMAX 100000
#define EMAX 1600000
#define HID 128
#define NGRAPH 64
#define SCAN_BLK 512

// ---------------- device scratch ----------------
__device__ __half g_xh[(size_t)NMAX * HID];    // fp16 copy of x
__device__ __half g_wt[HID * HID];             // fp16 W_gcn transposed: wt[n][k] = W[k][n]
__device__ __half g_yh[(size_t)NMAX * HID];    // fp16 UNscaled xt = x @ W_gcn
__device__ float g_dinv[NMAX];
__device__ int   g_deg[NMAX];
__device__ int   g_start[NMAX + 1];
__device__ int   g_cursor[NMAX];
__device__ int   g_csr_src[EMAX];
__device__ int   g_part[(NMAX + SCAN_BLK - 1) / SCAN_BLK];
__device__ int   g_partscan[(NMAX + SCAN_BLK - 1) / SCAN_BLK];
__device__ float g_gsum[NGRAPH * HID];
__device__ float g_gcnt[NGRAPH];
__device__ float g_gatesX[NGRAPH * 4 * HID];
__device__ __half g_whh_h[4 * HID * HID];      // fp16 copy of w_hh (64 KB, L1-resident)

// ---------------- fp16 conversions ----------------
__global__ void k_cvtx(const float* __restrict__ x, int total8) {  // total8 = N*HID/8
    int i = blockIdx.x * blockDim.x + threadIdx.x;
    if (i < total8) {
        float4 v0 = __ldg((const float4*)x + (size_t)i * 2);
        float4 v1 = __ldg((const float4*)x + (size_t)i * 2 + 1);
        __half2 h0 = __floats2half2_rn(v0.x, v0.y);
        __half2 h1 = __floats2half2_rn(v0.z, v0.w);
        __half2 h2 = __floats2half2_rn(v1.x, v1.y);
        __half2 h3 = __floats2half2_rn(v1.z, v1.w);
        uint4 p;
        p.x = *(unsigned*)&h0; p.y = *(unsigned*)&h1;
        p.z = *(unsigned*)&h2; p.w = *(unsigned*)&h3;
        *(uint4*)(g_xh + (size_t)i * 8) = p;
    }
}

__global__ void k_cvtw(const float* __restrict__ W, const float* __restrict__ w_hh) {
    int i = blockIdx.x * blockDim.x + threadIdx.x;
    if (i < HID * HID) {
        int n = i >> 7, k = i & 127;
        g_wt[n * HID + k] = __float2half(__ldg(&W[k * HID + n]));
    }
    if (i < 4 * HID * HID) g_whh_h[i] = __float2half(__ldg(&w_hh[i]));
}

// ---------------- init ----------------
__global__ void k_init(int N) {
    int i = blockIdx.x * blockDim.x + threadIdx.x;
    if (i < N) g_deg[i] = 0;
    if (i < NGRAPH * HID) g_gsum[i] = 0.f;
    if (i < NGRAPH) g_gcnt[i] = 0.f;
}

// ---------------- degree histogram over col ----------------
__global__ void k_deg(const int* __restrict__ ei, int E) {
    int e = blockIdx.x * blockDim.x + threadIdx.x;
    if (e < E) atomicAdd(&g_deg[__ldg(&ei[(size_t)E + e])], 1);
}

// ---------------- scan pass 1: block sums + dinv ----------------
__global__ __launch_bounds__(SCAN_BLK) void k_scan1(int N) {
    int i = blockIdx.x * SCAN_BLK + threadIdx.x;
    int v = (i < N) ? g_deg[i] : 0;
    if (i < N) g_dinv[i] = rsqrtf((float)v + 1.0f);
    int s = v;
    for (int o = 16; o > 0; o >>= 1) s += __shfl_down_sync(0xffffffffu, s, o);
    __shared__ int ws[16];
    int wid = threadIdx.x >> 5, lane = threadIdx.x & 31;
    if (lane == 0) ws[wid] = s;
    __syncthreads();
    if (threadIdx.x < 16) {
        int t = ws[threadIdx.x];
        for (int o = 8; o > 0; o >>= 1) t += __shfl_down_sync(0xffffu, t, o);
        if (threadIdx.x == 0) g_part[blockIdx.x] = t;
    }
}

// ---------------- scan pass 2 ----------------
__global__ __launch_bounds__(256) void k_scan2(int NB) {
    int tid = threadIdx.x;
    int v = (tid < NB) ? g_part[tid] : 0;
    int lane = tid & 31, wid = tid >> 5;
    int x = v;
    for (int o = 1; o < 32; o <<= 1) {
        int t = __shfl_up_sync(0xffffffffu, x, o);
        if (lane >= o) x += t;
    }
    __shared__ int ws[8];
    if (lane == 31) ws[wid] = x;
    __syncthreads();
    if (tid < 8) {
        int t = ws[tid];
        for (int o = 1; o < 8; o <<= 1) {
            int u = __shfl_up_sync(0xffu, t, o);
            if (tid >= o) t += u;
        }
        ws[tid] = t;
    }
    __syncthreads();
    int incl = x + (wid > 0 ? ws[wid - 1] : 0);
    if (tid < NB) g_partscan[tid] = incl - v;
}

// ---------------- scan pass 3 ----------------
__global__ __launch_bounds__(SCAN_BLK) void k_scan3(int N) {
    int i = blockIdx.x * SCAN_BLK + threadIdx.x;
    int v = (i < N) ? g_deg[i] : 0;
    int lane = threadIdx.x & 31, wid = threadIdx.x >> 5;
    int x = v;
    for (int o = 1; o < 32; o <<= 1) {
        int t = __shfl_up_sync(0xffffffffu, x, o);
        if (lane >= o) x += t;
    }
    __shared__ int ws[16];
    if (lane == 31) ws[wid] = x;
    __syncthreads();
    if (threadIdx.x < 16) {
        int t = ws[threadIdx.x];
        for (int o = 1; o < 16; o <<= 1) {
            int u = __shfl_up_sync(0xffffu, t, o);
            if (threadIdx.x >= o) t += u;
        }
        ws[threadIdx.x] = t;
    }
    __syncthreads();
    int base = g_partscan[blockIdx.x] + (wid > 0 ? ws[wid - 1] : 0);
    int excl = base + (x - v);
    if (i < N) { g_start[i] = excl; g_cursor[i] = excl; }
    if (i == N - 1) g_start[N] = excl + v;
}

// ---------------- CSR fill ----------------
__global__ void k_fill(const int* __restrict__ ei, int E) {
    int e = blockIdx.x * blockDim.x + threadIdx.x;
    if (e < E) {
        int row = __ldg(&ei[e]);
        int col = __ldg(&ei[(size_t)E + e]);
        int slot = atomicAdd(&g_cursor[col], 1);
        g_csr_src[slot] = row;
    }
}

// ---------------- tensor-core GEMM: yh[n] = fp16( x[n] @ W )  (no dinv!) ----------------
__global__ __launch_bounds__(256) void k_gemm_tc(int M) {
    __shared__ __half xs[128][72];
    __shared__ __half ws[128][72];
    int tid = threadIdx.x;
    int warp = tid >> 5, lane = tid & 31;
    int wm = (warp & 3) * 32;
    int wn = (warp >> 2) * 64;
    int g = lane >> 2, tig = lane & 3;
    int m0 = blockIdx.x * 128;

    float acc[2][8][4];
#pragma unroll
    for (int mt = 0; mt < 2; mt++)
#pragma unroll
        for (int nt = 0; nt < 8; nt++)
#pragma unroll
            for (int q = 0; q < 4; q++) acc[mt][nt][q] = 0.f;

    for (int kc = 0; kc < 2; kc++) {
#pragma unroll
        for (int i = 0; i < 4; i++) {
            int idx = i * 256 + tid;
            int r = idx >> 3, q = idx & 7;
            int grow = m0 + r;
            uint4 v = make_uint4(0u, 0u, 0u, 0u);
            if (grow < M)
                v = *(const uint4*)(g_xh + (size_t)grow * HID + kc * 64 + q * 8);
            *(uint4*)(&xs[r][q * 8]) = v;
            uint4 w = *(const uint4*)(g_wt + r * HID + kc * 64 + q * 8);
            *(uint4*)(&ws[r][q * 8]) = w;
        }
        __syncthreads();
#pragma unroll
        for (int ks = 0; ks < 4; ks++) {
            int k0 = ks * 16;
            unsigned a[2][4];
#pragma unroll
            for (int mt = 0; mt < 2; mt++) {
                int row = wm + mt * 16 + g;
                a[mt][0] = *(const unsigned*)(&xs[row][k0 + tig * 2]);
                a[mt][1] = *(const unsigned*)(&xs[row + 8][k0 + tig * 2]);
                a[mt][2] = *(const unsigned*)(&xs[row][k0 + tig * 2 + 8]);
                a[mt][3] = *(const unsigned*)(&xs[row + 8][k0 + tig * 2 + 8]);
            }
#pragma unroll
            for (int nt = 0; nt < 8; nt++) {
                int n = wn + nt * 8 + g;
                unsigned b0 = *(const unsigned*)(&ws[n][k0 + tig * 2]);
                unsigned b1 = *(const unsigned*)(&ws[n][k0 + tig * 2 + 8]);
#pragma unroll
                for (int mt = 0; mt < 2; mt++) {
                    float* c = acc[mt][nt];
                    asm volatile(
                        "mma.sync.aligned.m16n8k16.row.col.f32.f16.f16.f32 "
                        "{%0,%1,%2,%3}, {%4,%5,%6,%7}, {%8,%9}, {%0,%1,%2,%3};"
                        : "+f"(c[0]), "+f"(c[1]), "+f"(c[2]), "+f"(c[3])
                        : "r"(a[mt][0]), "r"(a[mt][1]), "r"(a[mt][2]), "r"(a[mt][3]),
                          "r"(b0), "r"(b1));
                }
            }
        }
        __syncthreads();
    }

#pragma unroll
    for (int mt = 0; mt < 2; mt++) {
        int row = m0 + wm + mt * 16 + g;
#pragma unroll
        for (int nt = 0; nt < 8; nt++) {
            int col = wn + nt * 8 + tig * 2;
            float* c = acc[mt][nt];
            if (row < M) {
                __half2 h = __floats2half2_rn(c[0], c[1]);
                *(__half2*)(g_yh + (size_t)row * HID + col) = h;
            }
            if (row + 8 < M) {
                __half2 h = __floats2half2_rn(c[2], c[3]);
                *(__half2*)(g_yh + (size_t)(row + 8) * HID + col) = h;
            }
        }
    }
}

// ---------------- fused gather-aggregate (dinv folded) + relu + mean-pool ----------------
__device__ __forceinline__ void pool_flush(int g, float4 run, float crun, int lane) {
    float* dst = g_gsum + g * HID + lane * 4;
    asm volatile("red.global.add.v4.f32 [%0], {%1,%2,%3,%4};"
                 :: "l"(dst), "f"(run.x), "f"(run.y), "f"(run.z), "f"(run.w) : "memory");
    if (lane == 0) atomicAdd(&g_gcnt[g], crun);
}

__device__ __forceinline__ void fma_row(float4& acc, float dv, uint2 r) {
    float2 lo = __half22float2(*(const __half2*)&r.x);
    float2 hi = __half22float2(*(const __half2*)&r.y);
    acc.x = fmaf(dv, lo.x, acc.x);
    acc.y = fmaf(dv, lo.y, acc.y);
    acc.z = fmaf(dv, hi.x, acc.z);
    acc.w = fmaf(dv, hi.y, acc.w);
}

__global__ __launch_bounds__(256) void k_agg(const int* __restrict__ batch,
                                             const float* __restrict__ b_gcn, int N) {
    int lane = threadIdx.x & 31, wid = threadIdx.x >> 5;
    int s0 = blockIdx.x * 128;
    int e0 = min(s0 + 128, N);
    int n0 = s0 + wid;
    if (n0 >= e0) return;

    float4 bb = __ldg((const float4*)(b_gcn + lane * 4));
    int curg = __ldg(&batch[n0]);
    float4 run = make_float4(0.f, 0.f, 0.f, 0.f);
    float crun = 0.f;

    for (int n = n0; n < e0; n += 8) {
        int gg = __ldg(&batch[n]);
        if (gg != curg) {
            pool_flush(curg, run, crun, lane);
            run = make_float4(0.f, 0.f, 0.f, 0.f);
            crun = 0.f;
            curg = gg;
        }
        int st = __ldg(&g_start[n]);
        int en = __ldg(&g_start[n + 1]);
        float dvn = __ldg(&g_dinv[n]);
        float4 acc = make_float4(0.f, 0.f, 0.f, 0.f);
        // self loop: dinv[n] * xt[n]
        fma_row(acc, dvn, __ldg((const uint2*)(g_yh + (size_t)n * HID) + lane));
        for (int base = st; base < en; base += 32) {
            int cnt = min(32, en - base);
            int id = (lane < cnt) ? __ldg(&g_csr_src[base + lane]) : 0;
            float dv = (lane < cnt) ? __ldg(&g_dinv[id]) : 0.f;
            int j = 0;
            for (; j + 8 <= cnt; j += 8) {
                int a[8]; float d[8]; uint2 r[8];
#pragma unroll
                for (int q = 0; q < 8; q++) {
                    a[q] = __shfl_sync(0xffffffffu, id, j + q);
                    d[q] = __shfl_sync(0xffffffffu, dv, j + q);
                }
#pragma unroll
                for (int q = 0; q < 8; q++)
                    r[q] = __ldg((const uint2*)(g_yh + (size_t)a[q] * HID) + lane);
#pragma unroll
                for (int q = 0; q < 8; q++) fma_row(acc, d[q], r[q]);
            }
            if (j + 4 <= cnt) {
                int a[4]; float d[4]; uint2 r[4];
#pragma unroll
                for (int q = 0; q < 4; q++) {
                    a[q] = __shfl_sync(0xffffffffu, id, j + q);
                    d[q] = __shfl_sync(0xffffffffu, dv, j + q);
                }
#pragma unroll
                for (int q = 0; q < 4; q++)
                    r[q] = __ldg((const uint2*)(g_yh + (size_t)a[q] * HID) + lane);
#pragma unroll
                for (int q = 0; q < 4; q++) fma_row(acc, d[q], r[q]);
                j += 4;
            }
            for (; j < cnt; j++) {
                int a0 = __shfl_sync(0xffffffffu, id, j);
                float d0 = __shfl_sync(0xffffffffu, dv, j);
                fma_row(acc, d0, __ldg((const uint2*)(g_yh + (size_t)a0 * HID) + lane));
            }
        }
        run.x += fmaxf(fmaf(acc.x, dvn, bb.x), 0.f);
        run.y += fmaxf(fmaf(acc.y, dvn, bb.y), 0.f);
        run.z += fmaxf(fmaf(acc.z, dvn, bb.z), 0.f);
        run.w += fmaxf(fmaf(acc.w, dvn, bb.w), 0.f);
        crun += 1.f;
    }
    pool_flush(curg, run, crun, lane);
}

// ---------------- input-side LSTM gates ----------------
__global__ __launch_bounds__(512) void k_gatesx(const float* __restrict__ w_ih,
                                                const float* __restrict__ b_ih,
                                                const float* __restrict__ b_hh) {
    __shared__ float p[HID];
    int t = blockIdx.x;
    if (threadIdx.x < HID) {
        float c = fmaxf(g_gcnt[t], 1.f);
        p[threadIdx.x] = g_gsum[t * HID + threadIdx.x] / c;
    }
    __syncthreads();
    int gg = threadIdx.x;
    const float4* wr = (const float4*)(w_ih + (size_t)gg * HID);
    float acc = __ldg(&b_ih[gg]) + __ldg(&b_hh[gg]);
#pragma unroll
    for (int j = 0; j < 32; j++) {
        float4 w = __ldg(wr + j);
        acc += w.x * p[j * 4] + w.y * p[j * 4 + 1] + w.z * p[j * 4 + 2] + w.w * p[j * 4 + 3];
    }
    g_gatesX[t * 512 + gg] = acc;
}

// ---------------- recurrent LSTM (fp16 weights, L1-resident, 4-way acc) + fused FC ----------------
__global__ __launch_bounds__(512) void k_lstm(const float* __restrict__ W_fc,
                                              const float* __restrict__ b_fc,
                                              float* __restrict__ out) {
    __shared__ float sh[HID];
    __shared__ float sg[4 * HID];
    int tid = threadIdx.x;
    float c = 0.f;
    if (tid < HID) sh[tid] = 0.f;
    __syncthreads();
    const uint4* wr = (const uint4*)(g_whh_h + (size_t)tid * HID);
    for (int t = 0; t < NGRAPH; t++) {
        float a0 = g_gatesX[t * 512 + tid], a1 = 0.f, a2 = 0.f, a3 = 0.f;
#pragma unroll
        for (int j = 0; j < 16; j += 4) {
#pragma unroll
            for (int u = 0; u < 4; u++) {
                uint4 w = __ldg(&wr[j + u]);
                float2 p0 = __half22float2(*(const __half2*)&w.x);
                float2 p1 = __half22float2(*(const __half2*)&w.y);
                float2 p2 = __half22float2(*(const __half2*)&w.z);
                float2 p3 = __half22float2(*(const __half2*)&w.w);
                const float* h = &sh[(j + u) * 8];
                a0 = fmaf(p0.x, h[0], a0); a1 = fmaf(p0.y, h[1], a1);
                a2 = fmaf(p1.x, h[2], a2); a3 = fmaf(p1.y, h[3], a3);
                a0 = fmaf(p2.x, h[4], a0); a1 = fmaf(p2.y, h[5], a1);
                a2 = fmaf(p3.x, h[6], a2); a3 = fmaf(p3.y, h[7], a3);
            }
        }
        sg[tid] = (a0 + a1) + (a2 + a3);
        __syncthreads();
        if (tid < HID) {
            float iv = 1.f / (1.f + __expf(-sg[tid]));
            float fv = 1.f / (1.f + __expf(-sg[HID + tid]));
            float gv = tanhf(sg[2 * HID + tid]);
            float ov = 1.f / (1.f + __expf(-sg[3 * HID + tid]));
            c = fv * c + iv * gv;
            sh[tid] = ov * tanhf(c);
        }
        __syncthreads();
        if (tid < 320) {
            int k = tid >> 5, lane = tid & 31;
            const float4* wf = (const float4*)(W_fc + (size_t)k * HID);
            float4 w = __ldg(&wf[lane]);
            float4 h4 = *(const float4*)&sh[lane * 4];
            float p = w.x * h4.x + w.y * h4.y + w.z * h4.z + w.w * h4.w;
            for (int o = 16; o > 0; o >>= 1) p += __shfl_down_sync(0xffffffffu, p, o);
            if (lane == 0) out[t * 10 + k] = p + __ldg(&b_fc[k]);
        }
    }
}

// ---------------- launch ----------------
extern "C" void kernel_launch(void* const* d_in, const int* in_sizes, int n_in,
                              void* d_out, int out_size) {
    const float* x      = (const float*)d_in[0];
    const int*   ei     = (const int*)d_in[1];
    const int*   batch  = (const int*)d_in[2];
    const float* W_gcn  = (const float*)d_in[3];
    const float* b_gcn  = (const float*)d_in[4];
    const float* w_ih   = (const float*)d_in[5];
    const float* w_hh   = (const float*)d_in[6];
    const float* b_ih   = (const float*)d_in[7];
    const float* b_hh   = (const float*)d_in[8];
    const float* W_fc   = (const float*)d_in[9];
    const float* b_fc   = (const float*)d_in[10];
    float* out = (float*)d_out;

    int N = in_sizes[2];       // 100000 nodes
    int E = in_sizes[1] / 2;   // 1600000 edges
    int NB = (N + SCAN_BLK - 1) / SCAN_BLK;

    static cudaStream_t s2 = nullptr;
    static cudaEvent_t ev0 = nullptr, evB = nullptr;
    if (s2 == nullptr) {
        cudaStreamCreate(&s2);
        cudaEventCreateWithFlags(&ev0, cudaEventDisableTiming);
        cudaEventCreateWithFlags(&evB, cudaEventDisableTiming);
    }

    // side stream: conversions + GEMM, fully independent of the degree/CSR chain
    cudaEventRecord(ev0, 0);
    cudaStreamWaitEvent(s2, ev0, 0);
    k_cvtx<<<(N * HID / 8 + 255) / 256, 256, 0, s2>>>(x, N * HID / 8);
    k_cvtw<<<(4 * HID * HID + 255) / 256, 256, 0, s2>>>(W_gcn, w_hh);
    k_gemm_tc<<<(N + 127) / 128, 256, 0, s2>>>(N);
    cudaEventRecord(evB, s2);

    // main stream: degree -> scan -> CSR fill
    k_init<<<(N + 255) / 256, 256>>>(N);
    k_deg<<<(E + 255) / 256, 256>>>(ei, E);
    k_scan1<<<NB, SCAN_BLK>>>(N);
    k_scan2<<<1, 256>>>(NB);
    k_scan3<<<NB, SCAN_BLK>>>(N);
    k_fill<<<(E + 255) / 256, 256>>>(ei, E);

    // join: agg needs CSR + dinv (main) and xt (s2)
    cudaStreamWaitEvent(0, evB, 0);
    k_agg<<<(N + 127) / 128, 256>>>(batch, b_gcn, N);
    k_gatesx<<<NGRAPH, 512>>>(w_ih, b_ih, b_hh);
    k_lstm<<<1, 512>>>(W_fc, b_fc, out);
}

// round 9
// speedup vs baseline: 1.0275x; 1.0275x over previous
#include <cuda_runtime.h>
#include <cuda_fp16.h>
#include <math.h>

// R9 = R8 resubmitted unchanged: the previous bench died in the GPU broker
// (container failure), so the R8 hypothesis (agg latency-hiding via 4x grid,
// 4-wide gather batching) is still unmeasured.

#define NMAX 100000
#define EMAX 1600000
#define HID 128
#define NGRAPH 64
#define SCAN_BLK 512

// ---------------- device scratch ----------------
__device__ __half g_xh[(size_t)NMAX * HID];    // fp16 copy of x
__device__ __half g_wt[HID * HID];             // fp16 W_gcn transposed: wt[n][k] = W[k][n]
__device__ __half g_yh[(size_t)NMAX * HID];    // fp16 UNscaled xt = x @ W_gcn
__device__ float g_dinv[NMAX];
__device__ int   g_deg[NMAX];
__device__ int   g_start[NMAX + 1];
__device__ int   g_cursor[NMAX];
__device__ int   g_csr_src[EMAX];
__device__ int   g_part[(NMAX + SCAN_BLK - 1) / SCAN_BLK];
__device__ int   g_partscan[(NMAX + SCAN_BLK - 1) / SCAN_BLK];
__device__ float g_gsum[NGRAPH * HID];
__device__ float g_gcnt[NGRAPH];
__device__ float g_gatesX[NGRAPH * 4 * HID];
__device__ __half g_whh_h[4 * HID * HID];      // fp16 copy of w_hh (64 KB, L1-resident)

// ---------------- fp16 conversions ----------------
__global__ void k_cvtx(const float* __restrict__ x, int total8) {
    int i = blockIdx.x * blockDim.x + threadIdx.x;
    if (i < total8) {
        float4 v0 = __ldg((const float4*)x + (size_t)i * 2);
        float4 v1 = __ldg((const float4*)x + (size_t)i * 2 + 1);
        __half2 h0 = __floats2half2_rn(v0.x, v0.y);
        __half2 h1 = __floats2half2_rn(v0.z, v0.w);
        __half2 h2 = __floats2half2_rn(v1.x, v1.y);
        __half2 h3 = __floats2half2_rn(v1.z, v1.w);
        uint4 p;
        p.x = *(unsigned*)&h0; p.y = *(unsigned*)&h1;
        p.z = *(unsigned*)&h2; p.w = *(unsigned*)&h3;
        *(uint4*)(g_xh + (size_t)i * 8) = p;
    }
}

__global__ void k_cvtw(const float* __restrict__ W, const float* __restrict__ w_hh) {
    int i = blockIdx.x * blockDim.x + threadIdx.x;
    if (i < HID * HID) {
        int n = i >> 7, k = i & 127;
        g_wt[n * HID + k] = __float2half(__ldg(&W[k * HID + n]));
    }
    if (i < 4 * HID * HID) g_whh_h[i] = __float2half(__ldg(&w_hh[i]));
}

// ---------------- init ----------------
__global__ void k_init(int N) {
    int i = blockIdx.x * blockDim.x + threadIdx.x;
    if (i < N) g_deg[i] = 0;
    if (i < NGRAPH * HID) g_gsum[i] = 0.f;
    if (i < NGRAPH) g_gcnt[i] = 0.f;
}

// ---------------- degree histogram over col ----------------
__global__ void k_deg(const int* __restrict__ ei, int E) {
    int e = blockIdx.x * blockDim.x + threadIdx.x;
    if (e < E) atomicAdd(&g_deg[__ldg(&ei[(size_t)E + e])], 1);
}

// ---------------- scan pass 1: block sums + dinv ----------------
__global__ __launch_bounds__(SCAN_BLK) void k_scan1(int N) {
    int i = blockIdx.x * SCAN_BLK + threadIdx.x;
    int v = (i < N) ? g_deg[i] : 0;
    if (i < N) g_dinv[i] = rsqrtf((float)v + 1.0f);
    int s = v;
    for (int o = 16; o > 0; o >>= 1) s += __shfl_down_sync(0xffffffffu, s, o);
    __shared__ int ws[16];
    int wid = threadIdx.x >> 5, lane = threadIdx.x & 31;
    if (lane == 0) ws[wid] = s;
    __syncthreads();
    if (threadIdx.x < 16) {
        int t = ws[threadIdx.x];
        for (int o = 8; o > 0; o >>= 1) t += __shfl_down_sync(0xffffu, t, o);
        if (threadIdx.x == 0) g_part[blockIdx.x] = t;
    }
}

// ---------------- scan pass 2 ----------------
__global__ __launch_bounds__(256) void k_scan2(int NB) {
    int tid = threadIdx.x;
    int v = (tid < NB) ? g_part[tid] : 0;
    int lane = tid & 31, wid = tid >> 5;
    int x = v;
    for (int o = 1; o < 32; o <<= 1) {
        int t = __shfl_up_sync(0xffffffffu, x, o);
        if (lane >= o) x += t;
    }
    __shared__ int ws[8];
    if (lane == 31) ws[wid] = x;
    __syncthreads();
    if (tid < 8) {
        int t = ws[tid];
        for (int o = 1; o < 8; o <<= 1) {
            int u = __shfl_up_sync(0xffu, t, o);
            if (tid >= o) t += u;
        }
        ws[tid] = t;
    }
    __syncthreads();
    int incl = x + (wid > 0 ? ws[wid - 1] : 0);
    if (tid < NB) g_partscan[tid] = incl - v;
}

// ---------------- scan pass 3 ----------------
__global__ __launch_bounds__(SCAN_BLK) void k_scan3(int N) {
    int i = blockIdx.x * SCAN_BLK + threadIdx.x;
    int v = (i < N) ? g_deg[i] : 0;
    int lane = threadIdx.x & 31, wid = threadIdx.x >> 5;
    int x = v;
    for (int o = 1; o < 32; o <<= 1) {
        int t = __shfl_up_sync(0xffffffffu, x, o);
        if (lane >= o) x += t;
    }
    __shared__ int ws[16];
    if (lane == 31) ws[wid] = x;
    __syncthreads();
    if (threadIdx.x < 16) {
        int t = ws[threadIdx.x];
        for (int o = 1; o < 16; o <<= 1) {
            int u = __shfl_up_sync(0xffffu, t, o);
            if (threadIdx.x >= o) t += u;
        }
        ws[threadIdx.x] = t;
    }
    __syncthreads();
    int base = g_partscan[blockIdx.x] + (wid > 0 ? ws[wid - 1] : 0);
    int excl = base + (x - v);
    if (i < N) { g_start[i] = excl; g_cursor[i] = excl; }
    if (i == N - 1) g_start[N] = excl + v;
}

// ---------------- CSR fill ----------------
__global__ void k_fill(const int* __restrict__ ei, int E) {
    int e = blockIdx.x * blockDim.x + threadIdx.x;
    if (e < E) {
        int row = __ldg(&ei[e]);
        int col = __ldg(&ei[(size_t)E + e]);
        int slot = atomicAdd(&g_cursor[col], 1);
        g_csr_src[slot] = row;
    }
}

// ---------------- tensor-core GEMM: yh[n] = fp16( x[n] @ W )  (no dinv) ----------------
__global__ __launch_bounds__(256) void k_gemm_tc(int M) {
    __shared__ __half xs[128][72];
    __shared__ __half ws[128][72];
    int tid = threadIdx.x;
    int warp = tid >> 5, lane = tid & 31;
    int wm = (warp & 3) * 32;
    int wn = (warp >> 2) * 64;
    int g = lane >> 2, tig = lane & 3;
    int m0 = blockIdx.x * 128;

    float acc[2][8][4];
#pragma unroll
    for (int mt = 0; mt < 2; mt++)
#pragma unroll
        for (int nt = 0; nt < 8; nt++)
#pragma unroll
            for (int q = 0; q < 4; q++) acc[mt][nt][q] = 0.f;

    for (int kc = 0; kc < 2; kc++) {
#pragma unroll
        for (int i = 0; i < 4; i++) {
            int idx = i * 256 + tid;
            int r = idx >> 3, q = idx & 7;
            int grow = m0 + r;
            uint4 v = make_uint4(0u, 0u, 0u, 0u);
            if (grow < M)
                v = *(const uint4*)(g_xh + (size_t)grow * HID + kc * 64 + q * 8);
            *(uint4*)(&xs[r][q * 8]) = v;
            uint4 w = *(const uint4*)(g_wt + r * HID + kc * 64 + q * 8);
            *(uint4*)(&ws[r][q * 8]) = w;
        }
        __syncthreads();
#pragma unroll
        for (int ks = 0; ks < 4; ks++) {
            int k0 = ks * 16;
            unsigned a[2][4];
#pragma unroll
            for (int mt = 0; mt < 2; mt++) {
                int row = wm + mt * 16 + g;
                a[mt][0] = *(const unsigned*)(&xs[row][k0 + tig * 2]);
                a[mt][1] = *(const unsigned*)(&xs[row + 8][k0 + tig * 2]);
                a[mt][2] = *(const unsigned*)(&xs[row][k0 + tig * 2 + 8]);
                a[mt][3] = *(const unsigned*)(&xs[row + 8][k0 + tig * 2 + 8]);
            }
#pragma unroll
            for (int nt = 0; nt < 8; nt++) {
                int n = wn + nt * 8 + g;
                unsigned b0 = *(const unsigned*)(&ws[n][k0 + tig * 2]);
                unsigned b1 = *(const unsigned*)(&ws[n][k0 + tig * 2 + 8]);
#pragma unroll
                for (int mt = 0; mt < 2; mt++) {
                    float* c = acc[mt][nt];
                    asm volatile(
                        "mma.sync.aligned.m16n8k16.row.col.f32.f16.f16.f32 "
                        "{%0,%1,%2,%3}, {%4,%5,%6,%7}, {%8,%9}, {%0,%1,%2,%3};"
                        : "+f"(c[0]), "+f"(c[1]), "+f"(c[2]), "+f"(c[3])
                        : "r"(a[mt][0]), "r"(a[mt][1]), "r"(a[mt][2]), "r"(a[mt][3]),
                          "r"(b0), "r"(b1));
                }
            }
        }
        __syncthreads();
    }

#pragma unroll
    for (int mt = 0; mt < 2; mt++) {
        int row = m0 + wm + mt * 16 + g;
#pragma unroll
        for (int nt = 0; nt < 8; nt++) {
            int col = wn + nt * 8 + tig * 2;
            float* c = acc[mt][nt];
            if (row < M) {
                __half2 h = __floats2half2_rn(c[0], c[1]);
                *(__half2*)(g_yh + (size_t)row * HID + col) = h;
            }
            if (row + 8 < M) {
                __half2 h = __floats2half2_rn(c[2], c[3]);
                *(__half2*)(g_yh + (size_t)(row + 8) * HID + col) = h;
            }
        }
    }
}

// ---------------- fused gather-aggregate (dinv folded) + relu + mean-pool ----------------
__device__ __forceinline__ void pool_flush(int g, float4 run, float crun, int lane) {
    float* dst = g_gsum + g * HID + lane * 4;
    asm volatile("red.global.add.v4.f32 [%0], {%1,%2,%3,%4};"
                 :: "l"(dst), "f"(run.x), "f"(run.y), "f"(run.z), "f"(run.w) : "memory");
    if (lane == 0) atomicAdd(&g_gcnt[g], crun);
}

__device__ __forceinline__ void fma_row(float4& acc, float dv, uint2 r) {
    float2 lo = __half22float2(*(const __half2*)&r.x);
    float2 hi = __half22float2(*(const __half2*)&r.y);
    acc.x = fmaf(dv, lo.x, acc.x);
    acc.y = fmaf(dv, lo.y, acc.y);
    acc.z = fmaf(dv, hi.x, acc.z);
    acc.w = fmaf(dv, hi.y, acc.w);
}

// 32 nodes per block (8 warps, 4 nodes/warp) -> ~3125 blocks for latency hiding.
__global__ __launch_bounds__(256) void k_agg(const int* __restrict__ batch,
                                             const float* __restrict__ b_gcn, int N) {
    int lane = threadIdx.x & 31, wid = threadIdx.x >> 5;
    int s0 = blockIdx.x * 32;
    int e0 = min(s0 + 32, N);
    int n0 = s0 + wid;
    if (n0 >= e0) return;

    float4 bb = __ldg((const float4*)(b_gcn + lane * 4));
    int curg = __ldg(&batch[n0]);
    float4 run = make_float4(0.f, 0.f, 0.f, 0.f);
    float crun = 0.f;

    for (int n = n0; n < e0; n += 8) {
        int gg = __ldg(&batch[n]);
        if (gg != curg) {
            pool_flush(curg, run, crun, lane);
            run = make_float4(0.f, 0.f, 0.f, 0.f);
            crun = 0.f;
            curg = gg;
        }
        int st = __ldg(&g_start[n]);
        int en = __ldg(&g_start[n + 1]);
        float dvn = __ldg(&g_dinv[n]);
        float4 acc = make_float4(0.f, 0.f, 0.f, 0.f);
        fma_row(acc, dvn, __ldg((const uint2*)(g_yh + (size_t)n * HID) + lane));  // self loop
        for (int base = st; base < en; base += 32) {
            int cnt = min(32, en - base);
            int id = (lane < cnt) ? __ldg(&g_csr_src[base + lane]) : 0;
            float dv = (lane < cnt) ? __ldg(&g_dinv[id]) : 0.f;
            int j = 0;
            for (; j + 4 <= cnt; j += 4) {
                int a0 = __shfl_sync(0xffffffffu, id, j);
                int a1 = __shfl_sync(0xffffffffu, id, j + 1);
                int a2 = __shfl_sync(0xffffffffu, id, j + 2);
                int a3 = __shfl_sync(0xffffffffu, id, j + 3);
                float d0 = __shfl_sync(0xffffffffu, dv, j);
                float d1 = __shfl_sync(0xffffffffu, dv, j + 1);
                float d2 = __shfl_sync(0xffffffffu, dv, j + 2);
                float d3 = __shfl_sync(0xffffffffu, dv, j + 3);
                uint2 r0 = __ldg((const uint2*)(g_yh + (size_t)a0 * HID) + lane);
                uint2 r1 = __ldg((const uint2*)(g_yh + (size_t)a1 * HID) + lane);
                uint2 r2 = __ldg((const uint2*)(g_yh + (size_t)a2 * HID) + lane);
                uint2 r3 = __ldg((const uint2*)(g_yh + (size_t)a3 * HID) + lane);
                fma_row(acc, d0, r0);
                fma_row(acc, d1, r1);
                fma_row(acc, d2, r2);
                fma_row(acc, d3, r3);
            }
            for (; j < cnt; j++) {
                int a0 = __shfl_sync(0xffffffffu, id, j);
                float d0 = __shfl_sync(0xffffffffu, dv, j);
                fma_row(acc, d0, __ldg((const uint2*)(g_yh + (size_t)a0 * HID) + lane));
            }
        }
        run.x += fmaxf(fmaf(acc.x, dvn, bb.x), 0.f);
        run.y += fmaxf(fmaf(acc.y, dvn, bb.y), 0.f);
        run.z += fmaxf(fmaf(acc.z, dvn, bb.z), 0.f);
        run.w += fmaxf(fmaf(acc.w, dvn, bb.w), 0.f);
        crun += 1.f;
    }
    pool_flush(curg, run, crun, lane);
}

// ---------------- input-side LSTM gates ----------------
__global__ __launch_bounds__(512) void k_gatesx(const float* __restrict__ w_ih,
                                                const float* __restrict__ b_ih,
                                                const float* __restrict__ b_hh) {
    __shared__ float p[HID];
    int t = blockIdx.x;
    if (threadIdx.x < HID) {
        float c = fmaxf(g_gcnt[t], 1.f);
        p[threadIdx.x] = g_gsum[t * HID + threadIdx.x] / c;
    }
    __syncthreads();
    int gg = threadIdx.x;
    const float4* wr = (const float4*)(w_ih + (size_t)gg * HID);
    float acc = __ldg(&b_ih[gg]) + __ldg(&b_hh[gg]);
#pragma unroll
    for (int j = 0; j < 32; j++) {
        float4 w = __ldg(wr + j);
        acc += w.x * p[j * 4] + w.y * p[j * 4 + 1] + w.z * p[j * 4 + 2] + w.w * p[j * 4 + 3];
    }
    g_gatesX[t * 512 + gg] = acc;
}

// ---------------- recurrent LSTM (fp16 weights, 4-way acc) + fused FC ----------------
__global__ __launch_bounds__(512) void k_lstm(const float* __restrict__ W_fc,
                                              const float* __restrict__ b_fc,
                                              float* __restrict__ out) {
    __shared__ float sh[HID];
    __shared__ float sg[4 * HID];
    int tid = threadIdx.x;
    float c = 0.f;
    if (tid < HID) sh[tid] = 0.f;
    __syncthreads();
    const uint4* wr = (const uint4*)(g_whh_h + (size_t)tid * HID);
    for (int t = 0; t < NGRAPH; t++) {
        float a0 = g_gatesX[t * 512 + tid], a1 = 0.f, a2 = 0.f, a3 = 0.f;
#pragma unroll
        for (int j = 0; j < 16; j += 4) {
#pragma unroll
            for (int u = 0; u < 4; u++) {
                uint4 w = __ldg(&wr[j + u]);
                float2 p0 = __half22float2(*(const __half2*)&w.x);
                float2 p1 = __half22float2(*(const __half2*)&w.y);
                float2 p2 = __half22float2(*(const __half2*)&w.z);
                float2 p3 = __half22float2(*(const __half2*)&w.w);
                const float* h = &sh[(j + u) * 8];
                a0 = fmaf(p0.x, h[0], a0); a1 = fmaf(p0.y, h[1], a1);
                a2 = fmaf(p1.x, h[2], a2); a3 = fmaf(p1.y, h[3], a3);
                a0 = fmaf(p2.x, h[4], a0); a1 = fmaf(p2.y, h[5], a1);
                a2 = fmaf(p3.x, h[6], a2); a3 = fmaf(p3.y, h[7], a3);
            }
        }
        sg[tid] = (a0 + a1) + (a2 + a3);
        __syncthreads();
        if (tid < HID) {
            float iv = 1.f / (1.f + __expf(-sg[tid]));
            float fv = 1.f / (1.f + __expf(-sg[HID + tid]));
            float gv = tanhf(sg[2 * HID + tid]);
            float ov = 1.f / (1.f + __expf(-sg[3 * HID + tid]));
            c = fv * c + iv * gv;
            sh[tid] = ov * tanhf(c);
        }
        __syncthreads();
        if (tid < 320) {
            int k = tid >> 5, lane = tid & 31;
            const float4* wf = (const float4*)(W_fc + (size_t)k * HID);
            float4 w = __ldg(&wf[lane]);
            float4 h4 = *(const float4*)&sh[lane * 4];
            float p = w.x * h4.x + w.y * h4.y + w.z * h4.z + w.w * h4.w;
            for (int o = 16; o > 0; o >>= 1) p += __shfl_down_sync(0xffffffffu, p, o);
            if (lane == 0) out[t * 10 + k] = p + __ldg(&b_fc[k]);
        }
    }
}

// ---------------- launch ----------------
extern "C" void kernel_launch(void* const* d_in, const int* in_sizes, int n_in,
                              void* d_out, int out_size) {
    const float* x      = (const float*)d_in[0];
    const int*   ei     = (const int*)d_in[1];
    const int*   batch  = (const int*)d_in[2];
    const float* W_gcn  = (const float*)d_in[3];
    const float* b_gcn  = (const float*)d_in[4];
    const float* w_ih   = (const float*)d_in[5];
    const float* w_hh   = (const float*)d_in[6];
    const float* b_ih   = (const float*)d_in[7];
    const float* b_hh   = (const float*)d_in[8];
    const float* W_fc   = (const float*)d_in[9];
    const float* b_fc   = (const float*)d_in[10];
    float* out = (float*)d_out;

    int N = in_sizes[2];       // 100000 nodes
    int E = in_sizes[1] / 2;   // 1600000 edges
    int NB = (N + SCAN_BLK - 1) / SCAN_BLK;

    static cudaStream_t s2 = nullptr;
    static cudaEvent_t ev0 = nullptr, evB = nullptr;
    if (s2 == nullptr) {
        cudaStreamCreate(&s2);
        cudaEventCreateWithFlags(&ev0, cudaEventDisableTiming);
        cudaEventCreateWithFlags(&evB, cudaEventDisableTiming);
    }

    // side stream: conversions + GEMM, independent of the degree/CSR chain
    cudaEventRecord(ev0, 0);
    cudaStreamWaitEvent(s2, ev0, 0);
    k_cvtx<<<(N * HID / 8 + 255) / 256, 256, 0, s2>>>(x, N * HID / 8);
    k_cvtw<<<(4 * HID * HID + 255) / 256, 256, 0, s2>>>(W_gcn, w_hh);
    k_gemm_tc<<<(N + 127) / 128, 256, 0, s2>>>(N);
    cudaEventRecord(evB, s2);

    // main stream: degree -> scan -> CSR fill
    k_init<<<(N + 255) / 256, 256>>>(N);
    k_deg<<<(E + 255) / 256, 256>>>(ei, E);
    k_scan1<<<NB, SCAN_BLK>>>(N);
    k_scan2<<<1, 256>>>(NB);
    k_scan3<<<NB, SCAN_BLK>>>(N);
    k_fill<<<(E + 255) / 256, 256>>>(ei, E);

    // join: agg needs CSR + dinv (main) and xt (s2)
    cudaStreamWaitEvent(0, evB, 0);
    k_agg<<<(N + 31) / 32, 256>>>(batch, b_gcn, N);
    k_gatesx<<<NGRAPH, 512>>>(w_ih, b_ih, b_hh);
    k_lstm<<<1, 512>>>(W_fc, b_fc, out);
}